// round 15
// baseline (speedup 1.0000x reference)
#include <cuda_runtime.h>
#include <math.h>

#define LS 65536      // layer size (256 x 256 sheet)
#define OS 2048       // out size (8 rows x 256 cols of the sheet)
#define SHEET_W 256
#define INF_RATE 0.1f
#define FILT 5
#define BUSY_ROWS 3328        // m < 3328 (rm <= 12) have nonzero weight rows
#define NBLK 104              // one CTA per SM, single wave; 104*32 = 3328 rows
#define NONBUSY (LS - BUSY_ROWS)   // 62208
#define CHUNK (NBLK * 256)         // 26624 elements per non-busy round

// Scratch (no cudaMalloc). Zero-initialized at module load.
// g_count/g_epoch are monotone across launches (epoch-stamped targets).
// g_acc is ping-ponged by epoch parity; block 0 zeroes the other parity after
// the rendezvous (kernel boundary orders it before the next launch's atomics).
__device__ double2      g_acc[2];
__device__ unsigned int g_count;
__device__ unsigned int g_pad[31];      // counter and epoch on separate lines
__device__ unsigned int g_epoch;

__device__ __forceinline__ unsigned int ld_acq(const unsigned int* p) {
    unsigned int v;
    asm volatile("ld.acquire.gpu.global.u32 %0, [%1];" : "=r"(v) : "l"(p) : "memory");
    return v;
}
__device__ __forceinline__ unsigned int ld_cg_u32(const unsigned int* p) {
    unsigned int v;
    asm volatile("ld.global.cg.u32 %0, [%1];" : "=r"(v) : "l"(p) : "memory");
    return v;
}
__device__ __forceinline__ double ld_cg_f64(const double* p) {
    double v;
    asm volatile("ld.global.cg.f64 %0, [%1];" : "=d"(v) : "l"(p) : "memory");
    return v;
}
__device__ __forceinline__ void red_rel_add_u32(unsigned int* p, unsigned int v) {
    asm volatile("red.release.gpu.global.add.u32 [%0], %1;" :: "l"(p), "r"(v) : "memory");
}
__device__ __forceinline__ void red_rel_add_f64(double* p, double v) {
    asm volatile("red.release.gpu.global.add.f64 [%0], %1;" :: "l"(p), "d"(v) : "memory");
}
__device__ __forceinline__ void st_rel(unsigned int* p, unsigned int v) {
    asm volatile("st.release.gpu.global.u32 [%0], %1;" :: "l"(p), "r"(v) : "memory");
}

// Single fused kernel, 104 blocks (one wave), one grid rendezvous.
// COALESCED window mapping: each warp owns 4 busy rows; for a row, the 32
// lanes split as lane = rn*4 + q -> 8 distinct 128B lines per row-load
// instead of 32 (4x fewer L1tex wavefronts than the per-thread-window map).
__global__ void __launch_bounds__(256) fused(
    const float* __restrict__ bu,
    const float* __restrict__ r_act,
    const float* __restrict__ r_out,
    const float* __restrict__ x,      // nextlayer_r_out [2048]
    const float* __restrict__ wt,     // weights [65536, 2048]
    float* __restrict__ out)          // [3*65536]: e | ra_thresholded | tanh
{
    const int bid  = blockIdx.x;
    const int tid  = threadIdx.x;
    const int lane = tid & 31;
    const int wid  = tid >> 5;

    __shared__ double wsum[8], wsq[8];
    __shared__ float  s_th;
    __shared__ unsigned int s_epoch;

    if (tid == 0) s_epoch = ld_cg_u32(&g_epoch);  // entry read precedes arrival

    // ================= FRONT-BATCHED LOADS (max MLP) =================
    // This warp owns 4 consecutive busy rows; all 4 share rm (4 | 256).
    const int rbase = bid * 32 + wid * 4;   // busy rows rbase..rbase+3
    const int rn    = lane >> 2;            // window (output sheet row) 0..7
    const int q     = lane & 3;             // float4 index within the window
    const int rm    = rbase >> 8;
    const bool live = (rn >= rm - FILT && rn <= rm + FILT);

    // W[m][n]==0.0f exactly outside the connectivity disc, so the fixed
    // aligned 16-float window only adds exact zeros.
    float4 W0, W1, W2, W3, X0, X1, X2, X3;
    W0 = W1 = W2 = W3 = X0 = X1 = X2 = X3 = make_float4(0.f, 0.f, 0.f, 0.f);
    {
        #pragma unroll
        for (int i = 0; i < 4; i++) {
            const int r  = rbase + i;
            const int cm = r & 255;
            int base = (cm - FILT) & ~3;
            if (base < 0) base = 0;
            if (base > SHEET_W - 16) base = SHEET_W - 16;
            const int off = rn * SHEET_W + base + q * 4;   // float index, 16B aligned
            if (live) {
                float4 wv = __ldg((const float4*)(wt + (size_t)r * OS + off));
                float4 xv = __ldg((const float4*)(x + off));
                if (i == 0) { W0 = wv; X0 = xv; }
                else if (i == 1) { W1 = wv; X1 = xv; }
                else if (i == 2) { W2 = wv; X2 = xv; }
                else { W3 = wv; X3 = xv; }
            }
        }
    }

    // Non-busy elementwise operands: 3 rounds (last partially predicated)
    const int i0 = bid * 256 + tid;              // round 0 index in [0, 62208)
    const int i1 = i0 + CHUNK;
    const int i2 = i0 + 2 * CHUNK;
    const bool h2 = (i2 < NONBUSY);
    const int m0 = BUSY_ROWS + i0, m1b = BUSY_ROWS + i1, m2 = BUSY_ROWS + i2;
    float ro0 = r_out[m0], rc0 = r_act[m0], b0 = bu[m0];
    float ro1 = r_out[m1b], rc1 = r_act[m1b], b1 = bu[m1b];
    float ro2 = 0.f, rc2 = 0.f, b2 = 0.f;
    if (h2) { ro2 = r_out[m2]; rc2 = r_act[m2]; b2 = bu[m2]; }

    // Busy-row operands prefetched by lanes 0..3 (row rbase+lane each)
    const bool isLeader = (lane < 4);
    const int  rowB = rbase + (lane & 3);
    float roB = 0.f, rcB = 0.f, bB = 0.f;
    if (isLeader) { roB = r_out[rowB]; rcB = r_act[rowB]; bB = bu[rowB]; }

    // ================= COMPUTE =================
    // Per-row partials (4 products each), then 32-lane butterfly reduce
    float p0, p1, p2, p3;
    p0 = fmaf(W0.x, X0.x, fmaf(W0.y, X0.y, fmaf(W0.z, X0.z, W0.w * X0.w)));
    p1 = fmaf(W1.x, X1.x, fmaf(W1.y, X1.y, fmaf(W1.z, X1.z, W1.w * X1.w)));
    p2 = fmaf(W2.x, X2.x, fmaf(W2.y, X2.y, fmaf(W2.z, X2.z, W2.w * X2.w)));
    p3 = fmaf(W3.x, X3.x, fmaf(W3.y, X3.y, fmaf(W3.z, X3.z, W3.w * X3.w)));
    #pragma unroll
    for (int o = 16; o > 0; o >>= 1) {
        p0 += __shfl_xor_sync(0xffffffffu, p0, o);
        p1 += __shfl_xor_sync(0xffffffffu, p1, o);
        p2 += __shfl_xor_sync(0xffffffffu, p2, o);
        p3 += __shfl_xor_sync(0xffffffffu, p3, o);
    }
    // All lanes now hold all 4 dots; lane i (0..3) owns row rbase+i
    const float dotSel = (lane == 0) ? p0 : (lane == 1) ? p1
                       : (lane == 2) ? p2 : p3;

    // Busy-row elementwise in place (lanes 0..3; no smem, no bar)
    float raB = 0.0f;
    if (isLeader) {
        float eB = roB - dotSel;
        raB = rcB + INF_RATE * (bB - eB);
        out[rowB] = eB;
    }

    // Non-busy elementwise (dot == 0 exactly)
    float e0 = ro0, e1 = ro1, e2v = ro2;
    float ra0 = rc0 + INF_RATE * (b0 - e0);
    float ra1 = rc1 + INF_RATE * (b1 - e1);
    float ra2 = h2 ? (rc2 + INF_RATE * (b2 - e2v)) : 0.0f;
    out[m0] = e0;
    out[m1b] = e1;
    if (h2) out[m2] = e2v;

    // ---- Warp reduction (double) -> smem -> warp-tree -> block atomics ----
    double s = (double)ra0 + (double)ra1 + (double)ra2 + (double)raB;
    double qq = (double)ra0 * ra0 + (double)ra1 * ra1
              + (double)ra2 * ra2 + (double)raB * raB;
    #pragma unroll
    for (int o = 16; o > 0; o >>= 1) {
        s  += __shfl_down_sync(0xffffffffu, s, o);
        qq += __shfl_down_sync(0xffffffffu, qq, o);
    }
    if (lane == 0) { wsum[wid] = s; wsq[wid] = qq; }
    __syncthreads();                        // also publishes s_epoch
    const unsigned int E = s_epoch;
    const int par = (int)(E & 1u);
    if (wid == 0) {
        // Warp 0: tree-reduce the 8 warp partials (no serial DADD chain)
        double bs = (lane < 8) ? wsum[lane] : 0.0;
        double bq = (lane < 8) ? wsq[lane]  : 0.0;
        #pragma unroll
        for (int o = 4; o > 0; o >>= 1) {
            bs += __shfl_down_sync(0xffffffffu, bs, o, 8);
            bq += __shfl_down_sync(0xffffffffu, bq, o, 8);
        }
        if (lane == 0) {
            red_rel_add_f64(&g_acc[par].x, bs);
            red_rel_add_f64(&g_acc[par].y, bq);
            red_rel_add_u32(&g_count, 1u);  // release orders the f64 adds
        }
    }

    // ---- Precompute tanh(ra) BEFORE the rendezvous (hidden under the wait).
    const float TANH_NEG1 = tanhf(-1.0f);   // constant-folded
    float t0 = tanhf(ra0);
    float t1 = tanhf(ra1);
    float t2 = h2 ? tanhf(ra2) : 0.0f;
    float tB = isLeader ? tanhf(raB) : 0.0f;

    // ---- Rendezvous: detect last arrival; each block computes threshold ----
    {
        const unsigned int t = (E + 1u) * (unsigned)NBLK;
        if (tid == 0) {
            while ((int)(ld_acq(&g_count) - t) < 0) { }
            double sum = ld_cg_f64(&g_acc[par].x);
            double sq  = ld_cg_f64(&g_acc[par].y);
            double mean = sum / (double)LS;
            double var  = (sq - sum * sum / (double)LS) / (double)(LS - 1);
            if (var < 0.0) var = 0.0;
            s_th = (float)(mean + 0.25 * sqrt(var));
            if (bid == 0) {
                g_acc[par ^ 1] = make_double2(0.0, 0.0);   // next launch's acc
                st_rel(&g_epoch, E + 1u);
            }
        }
        __syncthreads();                    // tid0's acquire + bar covers block
    }

    // ---- Tail: pure select + store ----
    const float th = s_th;
    {
        bool cut = (ra0 < th);
        out[LS + m0]     = cut ? -1.0f : ra0;
        out[2 * LS + m0] = cut ? TANH_NEG1 : t0;
    }
    {
        bool cut = (ra1 < th);
        out[LS + m1b]     = cut ? -1.0f : ra1;
        out[2 * LS + m1b] = cut ? TANH_NEG1 : t1;
    }
    if (h2) {
        bool cut = (ra2 < th);
        out[LS + m2]     = cut ? -1.0f : ra2;
        out[2 * LS + m2] = cut ? TANH_NEG1 : t2;
    }
    if (isLeader) {
        bool cut = (raB < th);
        out[LS + rowB]     = cut ? -1.0f : raB;
        out[2 * LS + rowB] = cut ? TANH_NEG1 : tB;
    }
}

extern "C" void kernel_launch(void* const* d_in, const int* in_sizes, int n_in,
                              void* d_out, int out_size)
{
    const float* bu    = (const float*)d_in[0];  // bu_errors [65536]
    const float* r_act = (const float*)d_in[1];  // r_act     [65536]
    const float* r_out = (const float*)d_in[2];  // r_out     [65536]
    const float* x     = (const float*)d_in[3];  // nextlayer_r_out [2048]
    const float* wt    = (const float*)d_in[4];  // weights [65536*2048]
    float* out = (float*)d_out;

    fused<<<NBLK, 256>>>(bu, r_act, r_out, x, wt, out);
}